// round 7
// baseline (speedup 1.0000x reference)
#include <cuda_runtime.h>
#include <cstdint>

// Transformer_66529043415377 — split-kernel design.
//
// Reference quirks: y clamped to [0, C-1]=[0,2], x to [0, H-1]=[0,511],
// raw [N,3] channel-interleaved output.
//
// Exact-zero structure (proved in R1-R6, rel_err == 0.0): with the
// reference's rounding order a pixel is nonzero ONLY when y = h + 64*dy
// lies in [0,2). Otherwise both clamped rows coincide, wb=-wa, wd=-wc
// exactly, and the left-assoc sum cancels to +0.0.
//
// Kernel Z: pure streaming zero-fill of the output (no loads -> saturates
//           the L2 write path, no latency chain).
// Kernel S: pure dy read stream, 16 px/thread with 4 front-batched
//           LDG.128 (MLP=4); ~99.7% of threads exit with no stores.
//           Rare active pixels overwrite their zeros with the bit-exact
//           bilinear result (scalar stores). Z -> S stream order gives
//           same-address ordering.

namespace {
constexpr int B  = 16;
constexpr int H  = 512;
constexpr int W  = 512;
constexpr int HW = H * W;            // 262144
constexpr int N  = B * HW;           // 4194304 pixels
constexpr int OUT_F4 = N * 3 / 4;    // 3,145,728 float4s

constexpr int ZTHREADS = 256;
constexpr int ZF4_PER_THREAD = 4;
constexpr int ZBLOCKS = OUT_F4 / (ZTHREADS * ZF4_PER_THREAD);   // 3072

constexpr int SPIX = 16;
constexpr int STHREADS = 128;
constexpr int SBLOCKS = N / (SPIX * STHREADS);                  // 2048
}

__global__ __launch_bounds__(ZTHREADS)
void zero_fill_kernel(float4* __restrict__ out)
{
    const int base = blockIdx.x * (ZTHREADS * ZF4_PER_THREAD) + threadIdx.x;
    const float4 z = make_float4(0.0f, 0.0f, 0.0f, 0.0f);
#pragma unroll
    for (int k = 0; k < ZF4_PER_THREAD; ++k)
        out[base + k * ZTHREADS] = z;
}

__global__ __launch_bounds__(STHREADS)
void scan_warp_kernel(const float* __restrict__ flow,
                      const float* __restrict__ pqf,
                      float* __restrict__ out)
{
    const int t = blockIdx.x * blockDim.x + threadIdx.x;
    const int i = t * SPIX;                     // base pixel index

    const int b   = i >> 18;                    // / HW
    const int rem = i & (HW - 1);
    const int h   = rem >> 9;                   // / W
    const int w   = rem & (W - 1);              // w..w+15 in-row (512%16==0)

    const float* fbase = flow + (size_t)b * 2 * HW + rem;
    const float* dyp   = fbase + HW;

    // 4 independent front-batched LDG.128 (MLP=4)
    const float4 d0 = *reinterpret_cast<const float4*>(dyp);
    const float4 d1 = *reinterpret_cast<const float4*>(dyp + 4);
    const float4 d2 = *reinterpret_cast<const float4*>(dyp + 8);
    const float4 d3 = *reinterpret_cast<const float4*>(dyp + 12);

    const float dys[16] = {d0.x, d0.y, d0.z, d0.w, d1.x, d1.y, d1.z, d1.w,
                           d2.x, d2.y, d2.z, d2.w, d3.x, d3.y, d3.z, d3.w};

    const float yf = (float)h;
    float yv[16];
    unsigned mask = 0;

#pragma unroll
    for (int j = 0; j < 16; ++j) {
        // fmaf bit-exact: dy*64 exact (power-of-two scale)
        const float y = __fmaf_rn(dys[j], 64.0f, yf);
        yv[j] = y;
        if (y >= 0.0f && y < 2.0f) mask |= (1u << j);
    }

    if (mask == 0) return;                      // all 16 px are exact zeros

    // Rare path: load dx, compute + scatter the active pixels.
    const float4 x0_ = *reinterpret_cast<const float4*>(fbase);
    const float4 x1_ = *reinterpret_cast<const float4*>(fbase + 4);
    const float4 x2_ = *reinterpret_cast<const float4*>(fbase + 8);
    const float4 x3_ = *reinterpret_cast<const float4*>(fbase + 12);
    const float dxs[16] = {x0_.x, x0_.y, x0_.z, x0_.w, x1_.x, x1_.y, x1_.z, x1_.w,
                           x2_.x, x2_.y, x2_.z, x2_.w, x3_.x, x3_.y, x3_.z, x3_.w};

    const int baseb = b << 9;                   // b * dim1 (=W=512)

#pragma unroll 1
    for (int j = 0; j < 16; ++j) {
        if (!(mask & (1u << j))) continue;

        const float y = yv[j];
        const float x = __fmaf_rn(dxs[j], 64.0f, (float)(w + j)); // bit-exact

        float x0f = floorf(x);
        float x1f = __fadd_rn(x0f, 1.0f);
        x0f = fminf(fmaxf(x0f, 0.0f), 511.0f);  // max_x = H-1 = 511
        x1f = fminf(fmaxf(x1f, 0.0f), 511.0f);

        // active => y in [0,2): clamps are no-ops, values match reference
        const float y0f = floorf(y);
        const float y1f = __fadd_rn(y0f, 1.0f);

        const int ix0 = (int)x0f;
        const int ix1 = (int)x1f;
        const int iy0 = (int)y0f;
        const int iy1 = (int)y1f;

        const int idx_a = baseb + iy0 * HW + ix0;
        const int idx_b = baseb + iy1 * HW + ix0;
        const int idx_c = baseb + iy0 * HW + ix1;
        const int idx_d = baseb + iy1 * HW + ix1;

        // single-rounded weight products (no contractible fma pattern)
        const float wxa = __fsub_rn(x1f, x);
        const float wxc = __fsub_rn(x, x0f);
        const float wya = __fsub_rn(y1f, y);
        const float wyb = __fsub_rn(y, y0f);
        const float wa = __fmul_rn(wxa, wya);
        const float wb = __fmul_rn(wxa, wyb);
        const float wc = __fmul_rn(wxc, wya);
        const float wd = __fmul_rn(wxc, wyb);

        const float* pa = pqf + (size_t)idx_a * 3;
        const float* pb = pqf + (size_t)idx_b * 3;
        const float* pc = pqf + (size_t)idx_c * 3;
        const float* pd = pqf + (size_t)idx_d * 3;

        float* op = out + (size_t)(i + j) * 3;
#pragma unroll
        for (int c = 0; c < 3; ++c) {
            // exact reference order: ((wa*A + wb*B) + wc*C) + wd*D,
            // each product individually rounded, no contraction
            const float pA = __fmul_rn(wa, __ldg(pa + c));
            const float pB = __fmul_rn(wb, __ldg(pb + c));
            const float pC = __fmul_rn(wc, __ldg(pc + c));
            const float pD = __fmul_rn(wd, __ldg(pd + c));
            op[c] = __fadd_rn(__fadd_rn(__fadd_rn(pA, pB), pC), pD);
        }
    }
}

extern "C" void kernel_launch(void* const* d_in, const int* in_sizes, int n_in,
                              void* d_out, int out_size)
{
    const float* flow = (const float*)d_in[0];
    const float* pqf  = (const float*)d_in[1];
    float* out        = (float*)d_out;

    zero_fill_kernel<<<ZBLOCKS, ZTHREADS>>>(reinterpret_cast<float4*>(out));
    scan_warp_kernel<<<SBLOCKS, STHREADS>>>(flow, pqf, out);
}

// round 10
// speedup vs baseline: 1.7139x; 1.7139x over previous
#include <cuda_runtime.h>
#include <cstdint>

// Transformer_66529043415377 — fused kernel, async-bulk zero stores.
//
// Reference quirks: y clamped to [0, C-1]=[0,2], x to [0, H-1]=[0,511],
// raw [N,3] channel-interleaved output.
//
// Exact-zero structure (bit-exact across R2-R7): with the reference's
// rounding order a pixel is nonzero ONLY when y = h + 64*dy lies in [0,2).
// Otherwise both clamped rows coincide, wb=-wa, wd=-wc exactly, and the
// left-assoc sum cancels to +0.0.
//
// Design: the 50 MB of zeros never touches the LSU/L1 store path.
// Each 256-thread CTA owns 1024 px = 12 KB of output; it zeroes a 12 KB
// SMEM buffer (STS, smem port) and issues ONE cp.async.bulk SMEM->GMEM
// (async proxy, L1-bypassing, drains at the chip L2 cap). Active pixels
// (~0.2%) are patched with scalar STGs after wait_group 0 + barrier.
//
// R10 fix: the R9 cta_any shared flag had an inter-warp store race
// (tid0's =0 could land after another warp's =1, silently dropping the
// patch phase). Replaced with __syncthreads_or — race-free HW reduction
// that doubles as the post-STS barrier.

namespace {
constexpr int B  = 16;
constexpr int H  = 512;
constexpr int W  = 512;
constexpr int HW = H * W;            // 262144
constexpr int N  = B * HW;           // 4194304 pixels
constexpr int PIX = 4;
constexpr int THREADS = 256;
constexpr int PX_PER_CTA = PIX * THREADS;        // 1024
constexpr int BYTES_PER_CTA = PX_PER_CTA * 3 * 4; // 12288
}

__device__ __forceinline__ uint32_t smem_u32(const void* p) {
    uint32_t a;
    asm("{ .reg .u64 t; cvta.to.shared.u64 t, %1; cvt.u32.u64 %0, t; }"
        : "=r"(a) : "l"(p));
    return a;
}

__global__ __launch_bounds__(THREADS)
void transformer_warp_kernel(const float* __restrict__ flow,
                             const float* __restrict__ pqf,
                             float* __restrict__ out)
{
    __shared__ float4 zbuf[BYTES_PER_CTA / 16];  // 12 KB of zeros

    const int tid = threadIdx.x;

    // Zero the SMEM tile (3 STS.128 per thread, smem port not L1tex).
    const float4 z = make_float4(0.0f, 0.0f, 0.0f, 0.0f);
    zbuf[tid]       = z;
    zbuf[tid + 256] = z;
    zbuf[tid + 512] = z;

    const int t = blockIdx.x * THREADS + tid;
    const int i = t * PIX;                      // base pixel index

    const int b   = i >> 18;                    // / HW
    const int rem = i & (HW - 1);
    const int h   = rem >> 9;                   // / W
    const int w   = rem & (W - 1);

    const float* fbase = flow + (size_t)b * 2 * HW + rem;
    const float4 dy4 = *reinterpret_cast<const float4*>(fbase + HW);

    const float yf = (float)h;

    // fmaf bit-exact: dy*64 exact (power-of-two scale)
    const float y0 = __fmaf_rn(dy4.x, 64.0f, yf);
    const float y1 = __fmaf_rn(dy4.y, 64.0f, yf);
    const float y2 = __fmaf_rn(dy4.z, 64.0f, yf);
    const float y3 = __fmaf_rn(dy4.w, 64.0f, yf);

    const bool a0 = (y0 >= 0.0f) && (y0 < 2.0f);
    const bool a1 = (y1 >= 0.0f) && (y1 < 2.0f);
    const bool a2 = (y2 >= 0.0f) && (y2 < 2.0f);
    const bool a3 = (y3 >= 0.0f) && (y3 < 2.0f);
    const bool any = a0 | a1 | a2 | a3;

    // Race-free block-wide OR; also orders all STS before the bulk store.
    const int cta_any = __syncthreads_or((int)any);

    // One bulk store of the CTA's whole 12 KB output span.
    if (tid == 0) {
        asm volatile("fence.proxy.async.shared::cta;" ::: "memory");
        const uint32_t saddr = smem_u32(zbuf);
        const float*   gdst  = out + (size_t)blockIdx.x * (BYTES_PER_CTA / 4);
        asm volatile(
            "cp.async.bulk.global.shared::cta.bulk_group [%0], [%1], %2;"
            :: "l"(gdst), "r"(saddr), "r"(BYTES_PER_CTA) : "memory");
        asm volatile("cp.async.bulk.commit_group;" ::: "memory");
        asm volatile("cp.async.bulk.wait_group 0;" ::: "memory");
    }

    if (cta_any == 0) return;                   // uniform: no patches needed

    __syncthreads();                            // zeros fully landed (tid0 waited)
    if (!any) return;

    // Rare path: patch active pixels over the zeros (bit-exact ref order).
    const float4 dx4 = *reinterpret_cast<const float4*>(fbase);
    const float dxs[4] = {dx4.x, dx4.y, dx4.z, dx4.w};
    const float yv[4]  = {y0, y1, y2, y3};
    const bool  act[4] = {a0, a1, a2, a3};

    const int baseb = b << 9;                   // b * dim1 (=W=512)

#pragma unroll
    for (int j = 0; j < 4; ++j) {
        if (!act[j]) continue;

        const float y = yv[j];
        const float x = __fmaf_rn(dxs[j], 64.0f, (float)(w + j)); // bit-exact

        float x0f = floorf(x);
        float x1f = __fadd_rn(x0f, 1.0f);
        x0f = fminf(fmaxf(x0f, 0.0f), 511.0f);  // max_x = H-1 = 511
        x1f = fminf(fmaxf(x1f, 0.0f), 511.0f);

        // active => y in [0,2): clamps no-ops; equals reference's y0,y1
        const float y0f = floorf(y);
        const float y1f = __fadd_rn(y0f, 1.0f);

        const int ix0 = (int)x0f;
        const int ix1 = (int)x1f;
        const int iy0 = (int)y0f;
        const int iy1 = (int)y1f;

        const int idx_a = baseb + iy0 * HW + ix0;
        const int idx_b = baseb + iy1 * HW + ix0;
        const int idx_c = baseb + iy0 * HW + ix1;
        const int idx_d = baseb + iy1 * HW + ix1;

        // single-rounded weight products (no contractible fma pattern)
        const float wxa = __fsub_rn(x1f, x);
        const float wxc = __fsub_rn(x, x0f);
        const float wya = __fsub_rn(y1f, y);
        const float wyb = __fsub_rn(y, y0f);
        const float wa = __fmul_rn(wxa, wya);
        const float wb = __fmul_rn(wxa, wyb);
        const float wc = __fmul_rn(wxc, wya);
        const float wd = __fmul_rn(wxc, wyb);

        const float* pa = pqf + (size_t)idx_a * 3;
        const float* pb = pqf + (size_t)idx_b * 3;
        const float* pc = pqf + (size_t)idx_c * 3;
        const float* pd = pqf + (size_t)idx_d * 3;

        float* op = out + (size_t)(i + j) * 3;
#pragma unroll
        for (int c = 0; c < 3; ++c) {
            // exact reference order: ((wa*A + wb*B) + wc*C) + wd*D,
            // each product individually rounded, no contraction
            const float pA = __fmul_rn(wa, __ldg(pa + c));
            const float pB = __fmul_rn(wb, __ldg(pb + c));
            const float pC = __fmul_rn(wc, __ldg(pc + c));
            const float pD = __fmul_rn(wd, __ldg(pd + c));
            op[c] = __fadd_rn(__fadd_rn(__fadd_rn(pA, pB), pC), pD);
        }
    }
}

extern "C" void kernel_launch(void* const* d_in, const int* in_sizes, int n_in,
                              void* d_out, int out_size)
{
    const float* flow = (const float*)d_in[0];
    const float* pqf  = (const float*)d_in[1];
    float* out        = (float*)d_out;

    const int blocks = N / PX_PER_CTA;          // 4096
    transformer_warp_kernel<<<blocks, THREADS>>>(flow, pqf, out);
}

// round 12
// speedup vs baseline: 1.7512x; 1.0217x over previous
#include <cuda_runtime.h>
#include <cstdint>

// Transformer_66529043415377 — fused kernel, async-bulk zero stores, v2.
//
// Reference quirks: y clamped to [0, C-1]=[0,2], x to [0, H-1]=[0,511],
// raw [N,3] channel-interleaved output.
//
// Exact-zero structure (bit-exact since R2): with the reference's rounding
// order a pixel is nonzero ONLY when y = h + 64*dy lies in [0,2). Otherwise
// both clamped rows coincide, wb=-wa, wd=-wc exactly, and the left-assoc
// sum cancels to +0.0.
//
// R11 changes vs R10 (13.5 us):
//  * bulk store issued right after the STS barrier, BEFORE the dy results
//    are consumed -> 6 KB drain overlaps the ~600cy dy-load latency.
//  * finer CTAs: 128 threads / 6 KB tile / 8192 blocks (same 32K warps).
//  * wait_group 0 stays unconditional on tid0: exiting with a pending bulk
//    read of SMEM would race a newly-scheduled CTA overwriting the source.

namespace {
constexpr int B  = 16;
constexpr int H  = 512;
constexpr int W  = 512;
constexpr int HW = H * W;            // 262144
constexpr int N  = B * HW;           // 4194304 pixels
constexpr int PIX = 4;
constexpr int THREADS = 128;
constexpr int PX_PER_CTA = PIX * THREADS;         // 512
constexpr int BYTES_PER_CTA = PX_PER_CTA * 3 * 4; // 6144
}

__device__ __forceinline__ uint32_t smem_u32(const void* p) {
    uint32_t a;
    asm("{ .reg .u64 t; cvta.to.shared.u64 t, %1; cvt.u32.u64 %0, t; }"
        : "=r"(a) : "l"(p));
    return a;
}

__global__ __launch_bounds__(THREADS)
void transformer_warp_kernel(const float* __restrict__ flow,
                             const float* __restrict__ pqf,
                             float* __restrict__ out)
{
    __shared__ float4 zbuf[BYTES_PER_CTA / 16];  // 6 KB of zeros

    const int tid = threadIdx.x;

    const int t = blockIdx.x * THREADS + tid;
    const int i = t * PIX;                      // base pixel index

    const int b   = i >> 18;                    // / HW
    const int rem = i & (HW - 1);
    const int h   = rem >> 9;                   // / W
    const int w   = rem & (W - 1);

    // Issue the dy load FIRST so it flies across the barrier + bulk issue.
    const float* fbase = flow + (size_t)b * 2 * HW + rem;
    const float4 dy4 = *reinterpret_cast<const float4*>(fbase + HW);

    // Zero the SMEM tile (3 STS.128 per thread).
    const float4 z = make_float4(0.0f, 0.0f, 0.0f, 0.0f);
    zbuf[tid]       = z;
    zbuf[tid + 128] = z;
    zbuf[tid + 256] = z;

    __syncthreads();                            // STS complete -> bulk may read

    // One bulk store of the CTA's whole 6 KB output span (async proxy,
    // bypasses L1). Issued before dy is consumed: drain overlaps compute.
    if (tid == 0) {
        asm volatile("fence.proxy.async.shared::cta;" ::: "memory");
        const uint32_t saddr = smem_u32(zbuf);
        const float*   gdst  = out + (size_t)blockIdx.x * (BYTES_PER_CTA / 4);
        asm volatile(
            "cp.async.bulk.global.shared::cta.bulk_group [%0], [%1], %2;"
            :: "l"(gdst), "r"(saddr), "r"(BYTES_PER_CTA) : "memory");
        asm volatile("cp.async.bulk.commit_group;" ::: "memory");
    }

    const float yf = (float)h;

    // fmaf bit-exact: dy*64 exact (power-of-two scale)
    const float y0 = __fmaf_rn(dy4.x, 64.0f, yf);
    const float y1 = __fmaf_rn(dy4.y, 64.0f, yf);
    const float y2 = __fmaf_rn(dy4.z, 64.0f, yf);
    const float y3 = __fmaf_rn(dy4.w, 64.0f, yf);

    const bool a0 = (y0 >= 0.0f) && (y0 < 2.0f);
    const bool a1 = (y1 >= 0.0f) && (y1 < 2.0f);
    const bool a2 = (y2 >= 0.0f) && (y2 < 2.0f);
    const bool a3 = (y3 >= 0.0f) && (y3 < 2.0f);
    const bool any = a0 | a1 | a2 | a3;

    // Race-free block-wide OR.
    const int cta_any = __syncthreads_or((int)any);

    // SMEM-reuse safety: the bulk op reads zbuf asynchronously; the CTA may
    // not exit until it has drained, or a successor CTA could overwrite the
    // source mid-copy. tid0 waits; other threads may exit.
    if (tid == 0)
        asm volatile("cp.async.bulk.wait_group 0;" ::: "memory");

    if (cta_any == 0) return;                   // uniform: no patches needed

    __syncthreads();                            // zeros fully landed
    if (!any) return;

    // Rare path: patch active pixels over the zeros (bit-exact ref order).
    const float4 dx4 = *reinterpret_cast<const float4*>(fbase);
    const float dxs[4] = {dx4.x, dx4.y, dx4.z, dx4.w};
    const float yv[4]  = {y0, y1, y2, y3};
    const bool  act[4] = {a0, a1, a2, a3};

    const int baseb = b << 9;                   // b * dim1 (=W=512)

#pragma unroll
    for (int j = 0; j < 4; ++j) {
        if (!act[j]) continue;

        const float y = yv[j];
        const float x = __fmaf_rn(dxs[j], 64.0f, (float)(w + j)); // bit-exact

        float x0f = floorf(x);
        float x1f = __fadd_rn(x0f, 1.0f);
        x0f = fminf(fmaxf(x0f, 0.0f), 511.0f);  // max_x = H-1 = 511
        x1f = fminf(fmaxf(x1f, 0.0f), 511.0f);

        // active => y in [0,2): clamps no-ops; equals reference's y0,y1
        const float y0f = floorf(y);
        const float y1f = __fadd_rn(y0f, 1.0f);

        const int ix0 = (int)x0f;
        const int ix1 = (int)x1f;
        const int iy0 = (int)y0f;
        const int iy1 = (int)y1f;

        const int idx_a = baseb + iy0 * HW + ix0;
        const int idx_b = baseb + iy1 * HW + ix0;
        const int idx_c = baseb + iy0 * HW + ix1;
        const int idx_d = baseb + iy1 * HW + ix1;

        // single-rounded weight products (no contractible fma pattern)
        const float wxa = __fsub_rn(x1f, x);
        const float wxc = __fsub_rn(x, x0f);
        const float wya = __fsub_rn(y1f, y);
        const float wyb = __fsub_rn(y, y0f);
        const float wa = __fmul_rn(wxa, wya);
        const float wb = __fmul_rn(wxa, wyb);
        const float wc = __fmul_rn(wxc, wya);
        const float wd = __fmul_rn(wxc, wyb);

        const float* pa = pqf + (size_t)idx_a * 3;
        const float* pb = pqf + (size_t)idx_b * 3;
        const float* pc = pqf + (size_t)idx_c * 3;
        const float* pd = pqf + (size_t)idx_d * 3;

        float* op = out + (size_t)(i + j) * 3;
#pragma unroll
        for (int c = 0; c < 3; ++c) {
            // exact reference order: ((wa*A + wb*B) + wc*C) + wd*D,
            // each product individually rounded, no contraction
            const float pA = __fmul_rn(wa, __ldg(pa + c));
            const float pB = __fmul_rn(wb, __ldg(pb + c));
            const float pC = __fmul_rn(wc, __ldg(pc + c));
            const float pD = __fmul_rn(wd, __ldg(pd + c));
            op[c] = __fadd_rn(__fadd_rn(__fadd_rn(pA, pB), pC), pD);
        }
    }
}

extern "C" void kernel_launch(void* const* d_in, const int* in_sizes, int n_in,
                              void* d_out, int out_size)
{
    const float* flow = (const float*)d_in[0];
    const float* pqf  = (const float*)d_in[1];
    float* out        = (float*)d_out;

    const int blocks = N / PX_PER_CTA;          // 8192
    transformer_warp_kernel<<<blocks, THREADS>>>(flow, pqf, out);
}